// round 11
// baseline (speedup 1.0000x reference)
#include <cuda_runtime.h>
#include <math.h>
#include <cstdint>

#define BATCH 512
#define NTOK  16
#define CDIM  256
#define KCODE 8192
#define NSTAGE 16
#define BNC (BATCH*NTOK*CDIM)   // 2097152

// ---------------- device globals (scratch) ----------------
__device__ float  g_fres[BNC];
__device__ float  g_fhat[BNC];
__device__ float  g_rest[BATCH*NTOK*CDIM];
__device__ float  g_t1[BATCH*NTOK];
__device__ float  g_esq[KCODE];
__device__ int    g_idx[BATCH*NTOK];
__device__ float  g_pd[BATCH*NTOK*64];
__device__ int    g_pi[BATCH*NTOK*64];
__device__ double g_m[NSTAGE];

// ---------------- packed f32x2 helpers ----------------
__device__ __forceinline__ void ffma2(unsigned long long& acc, unsigned long long a, unsigned long long b) {
    asm("fma.rn.f32x2 %0, %1, %2, %0;" : "+l"(acc) : "l"(a), "l"(b));
}
__device__ __forceinline__ unsigned long long pack_dup(float v) {
    unsigned long long r;
    asm("mov.b64 %0, {%1, %1};" : "=l"(r) : "r"(__float_as_uint(v)));
    return r;
}
__device__ __forceinline__ void unpack2(unsigned long long p, float& lo, float& hi) {
    uint32_t a, b;
    asm("mov.b64 {%0, %1}, %2;" : "=r"(a), "=r"(b) : "l"(p));
    lo = __uint_as_float(a); hi = __uint_as_float(b);
}

// ---------------- init ----------------
__global__ void init_kernel(const float* __restrict__ f) {
    size_t i = (size_t)blockIdx.x * 256 + threadIdx.x;
    g_fres[i] = f[i];
    g_fhat[i] = 0.0f;
    if (i < NSTAGE) g_m[i] = 0.0;
}

// ---------------- e_sq ----------------
__global__ void esq_kernel(const float* __restrict__ emb) {
    int gw = (blockIdx.x * blockDim.x + threadIdx.x) >> 5;
    int lane = threadIdx.x & 31;
    if (gw >= KCODE) return;
    float s = 0.0f;
    const float* row = emb + (size_t)gw * CDIM;
    #pragma unroll
    for (int c = lane; c < CDIM; c += 32) { float v = row[c]; s = __fmaf_rn(v, v, s); }
    #pragma unroll
    for (int o = 16; o; o >>= 1) s += __shfl_down_sync(0xffffffffu, s, o);
    if (lane == 0) g_esq[gw] = s;
}

// ---------------- pool + t1 ----------------
__global__ void pool_kernel(int pn) {
    int row = blockIdx.x;
    int b = row / pn, p = row - b * pn;
    int s = (p * NTOK) / pn;
    int e = ((p + 1) * NTOK + pn - 1) / pn;
    float w = (float)(1.0 / (double)(e - s));
    int c = threadIdx.x;
    float acc = 0.0f;
    for (int n = s; n < e; n++)
        acc = __fmaf_rn(w, g_fres[((size_t)b * NTOK + n) * CDIM + c], acc);
    g_rest[(size_t)row * CDIM + c] = acc;

    float sq = __fmul_rn(acc, acc);
    __shared__ float sm[8];
    int lane = threadIdx.x & 31, wid = threadIdx.x >> 5;
    #pragma unroll
    for (int o = 16; o; o >>= 1) sq += __shfl_down_sync(0xffffffffu, sq, o);
    if (lane == 0) sm[wid] = sq;
    __syncthreads();
    if (wid == 0) {
        float v = (lane < 8) ? sm[lane] : 0.0f;
        #pragma unroll
        for (int o = 4; o; o >>= 1) v += __shfl_down_sync(0xffffffffu, v, o);
        if (lane == 0) g_t1[row] = v;
    }
}

// ---------------- FFMA2 distance GEMM + fused argmin (v2) ----------------
// Tile 128 rows x 128 codes; K in 8 chunks of 32. 256 threads, 8x8 microtile.
// A stored DUPLICATED in smem (As2[c][2m]=As2[c][2m+1]) so the A-broadcast is a
// plain LDS.64 — no per-iter MOVs. Double-buffered smem: one barrier per chunk.
// FMA chain order identical to round-9/round-1 => bit-identical output.
#define A2PITCH 258
#define BPITCH  130
#define A2BUF   (32 * A2PITCH)           // 8256 floats per buffer
#define BBUF    (32 * BPITCH)            // 4160 floats per buffer
#define BS_OFF  (2 * A2BUF)              // 16512
#define DIST_SMEM ((BS_OFF + 2 * BBUF) * 4)   // 99328 bytes

__global__ __launch_bounds__(256, 2) void dist_kernel(const float* __restrict__ emb) {
    extern __shared__ __align__(16) float sh[];
    float* As2 = sh;
    float* Bsm = sh + BS_OFF;
    int r0 = blockIdx.x * 128;
    int k0 = blockIdx.y * 128;
    int t  = threadIdx.x;
    int tx = t & 15, ty = t >> 4;

    unsigned long long acc[8][4];
    #pragma unroll
    for (int i = 0; i < 8; i++)
        #pragma unroll
        for (int j = 0; j < 4; j++) acc[i][j] = 0ull;

    float4 sa[4], sb[4];
    auto ldg_stage = [&](int cb) {
        #pragma unroll
        for (int p = 0; p < 4; p++) {
            int id = t + 256 * p;
            int m = id >> 3, c4 = id & 7;
            sa[p] = *(const float4*)(g_rest + (size_t)(r0 + m) * CDIM + cb * 32 + c4 * 4);
            sb[p] = *(const float4*)(emb    + (size_t)(k0 + m) * CDIM + cb * 32 + c4 * 4);
        }
    };
    auto sts_stage = [&](int buf) {
        float* A = As2 + buf * A2BUF;
        float* B = Bsm + buf * BBUF;
        #pragma unroll
        for (int p = 0; p < 4; p++) {
            int id = t + 256 * p;
            int m = id >> 3, c4 = id & 7;
            const float* av = (const float*)&sa[p];
            const float* bv = (const float*)&sb[p];
            #pragma unroll
            for (int x = 0; x < 4; x++) {
                *(unsigned long long*)&A[(c4 * 4 + x) * A2PITCH + 2 * m] = pack_dup(av[x]);
                B[(c4 * 4 + x) * BPITCH + m] = bv[x];
            }
        }
    };

    ldg_stage(0);
    sts_stage(0);
    __syncthreads();

    for (int cb = 0; cb < 8; cb++) {
        int buf = cb & 1;
        if (cb < 7) ldg_stage(cb + 1);     // LDG overlaps compute
        const float* A = As2 + buf * A2BUF;
        const float* B = Bsm + buf * BBUF;
        #pragma unroll
        for (int c = 0; c < 32; c++) {
            unsigned long long bp[4];
            #pragma unroll
            for (int j = 0; j < 4; j++)
                bp[j] = *(const unsigned long long*)&B[c * BPITCH + 2 * tx + 32 * j];
            #pragma unroll
            for (int i = 0; i < 8; i++) {
                unsigned long long ap =
                    *(const unsigned long long*)&A[c * A2PITCH + 2 * (ty + 16 * i)];
                #pragma unroll
                for (int j = 0; j < 4; j++)
                    ffma2(acc[i][j], ap, bp[j]);
            }
        }
        if (cb < 7) sts_stage(buf ^ 1);    // fill other buffer
        __syncthreads();
    }

    // ---- epilogue: d = fl(fl(t1+e_sq) - 2*dot); argmin, first-index ties ----
    #pragma unroll
    for (int i = 0; i < 8; i++) {
        int row = r0 + ty + 16 * i;
        float t1 = g_t1[row];
        float bd = INFINITY;
        int   bk = 0x7fffffff;
        #pragma unroll
        for (int j = 0; j < 4; j++) {
            float lo, hi;
            unpack2(acc[i][j], lo, hi);
            int k = k0 + 2 * tx + 32 * j;
            float tt0 = __fadd_rn(t1, g_esq[k]);
            float d0  = __fmaf_rn(-2.0f, lo, tt0);
            if (d0 < bd || (d0 == bd && k < bk)) { bd = d0; bk = k; }
            float tt1 = __fadd_rn(t1, g_esq[k + 1]);
            float d1  = __fmaf_rn(-2.0f, hi, tt1);
            if (d1 < bd || (d1 == bd && (k + 1) < bk)) { bd = d1; bk = k + 1; }
        }
        #pragma unroll
        for (int o = 8; o; o >>= 1) {
            float od = __shfl_down_sync(0xffffffffu, bd, o, 16);
            int   ok = __shfl_down_sync(0xffffffffu, bk, o, 16);
            if (od < bd || (od == bd && ok < bk)) { bd = od; bk = ok; }
        }
        if (tx == 0) {
            g_pd[(size_t)row * 64 + blockIdx.y] = bd;
            g_pi[(size_t)row * 64 + blockIdx.y] = bk;
        }
    }
}

// ---------------- reduce argmin across 64 k-blocks ----------------
__global__ void argmin_reduce_kernel() {
    int row = blockIdx.x * 8 + threadIdx.y;
    int l = threadIdx.x;
    size_t base = (size_t)row * 64;
    float bd = g_pd[base + l];      int bk = g_pi[base + l];
    float d2 = g_pd[base + l + 32]; int k2 = g_pi[base + l + 32];
    if (d2 < bd || (d2 == bd && k2 < bk)) { bd = d2; bk = k2; }
    #pragma unroll
    for (int o = 16; o; o >>= 1) {
        float od = __shfl_down_sync(0xffffffffu, bd, o);
        int   ok = __shfl_down_sync(0xffffffffu, bk, o);
        if (od < bd || (od == bd && ok < bk)) { bd = od; bk = ok; }
    }
    if (l == 0) g_idx[row] = bk;
}

// ---------------- gather + upsample + update + stats ----------------
__global__ void update_kernel(const float* __restrict__ f, const float* __restrict__ emb,
                              int pn, int stage) {
    int bn = blockIdx.x;
    int n = bn & 15, b = bn >> 4;
    int c = threadIdx.x;

    double scale = (double)pn / 16.0;
    double pos = ((double)n + 0.5) * scale - 0.5;
    if (pos < 0.0) pos = 0.0;
    int i0 = (int)floor(pos);
    if (i0 > pn - 1) i0 = pn - 1;
    int i1 = (i0 + 1 < pn) ? i0 + 1 : pn - 1;
    double frac = pos - (double)i0;

    int base = b * pn;
    float hv;
    if (i1 == i0) {
        float wc = (float)((double)((float)(1.0 - frac)) + frac);
        int k0 = g_idx[base + i0];
        hv = __fmul_rn(wc, emb[(size_t)k0 * CDIM + c]);
    } else {
        float w0 = (float)(1.0 - frac);
        float w1 = (float)frac;
        int k0 = g_idx[base + i0];
        int k1 = g_idx[base + i1];
        hv = __fadd_rn(__fmul_rn(w0, emb[(size_t)k0 * CDIM + c]),
                       __fmul_rn(w1, emb[(size_t)k1 * CDIM + c]));
    }

    size_t off = (size_t)bn * CDIM + c;
    float fh = __fadd_rn(g_fhat[off], hv);
    g_fhat[off] = fh;
    g_fres[off] = __fadd_rn(g_fres[off], -hv);

    float diff = __fadd_rn(fh, -f[off]);
    double v = (double)diff * (double)diff;

    __shared__ double sm[8];
    int lane = threadIdx.x & 31, wid = threadIdx.x >> 5;
    #pragma unroll
    for (int o = 16; o; o >>= 1) v += __shfl_down_sync(0xffffffffu, v, o);
    if (lane == 0) sm[wid] = v;
    __syncthreads();
    if (wid == 0) {
        double w = (lane < 8) ? sm[lane] : 0.0;
        #pragma unroll
        for (int o = 4; o; o >>= 1) w += __shfl_down_sync(0xffffffffu, w, o);
        if (lane == 0) atomicAdd(&g_m[stage], w);
    }
}

// ---------------- outputs ----------------
__global__ void out_main_kernel(const float* __restrict__ f, float* __restrict__ out) {
    size_t i = (size_t)blockIdx.x * 256 + threadIdx.x;
    out[i] = __fadd_rn(__fadd_rn(g_fhat[i], -f[i]), f[i]);
}
__global__ void out_scalar_kernel(float* __restrict__ out) {
    if (threadIdx.x == 0 && blockIdx.x == 0) {
        float c = 0.0f, q = 0.0f;
        for (int s = 0; s < NSTAGE; s++) {
            float m = (float)(g_m[s] * (1.0 / 2097152.0));
            c = __fadd_rn(c, __fmul_rn(0.25f, m));
            q = __fadd_rn(q, m);
        }
        out[BNC]     = __fdiv_rn(c, 16.0f);
        out[BNC + 1] = __fdiv_rn(q, 16.0f);
    }
}

// ---------------- launch ----------------
extern "C" void kernel_launch(void* const* d_in, const int* in_sizes, int n_in,
                              void* d_out, int out_size) {
    const float* f   = (const float*)d_in[0];
    const float* emb = (const float*)d_in[1];
    float* out = (float*)d_out;

    cudaFuncSetAttribute(dist_kernel, cudaFuncAttributeMaxDynamicSharedMemorySize, DIST_SMEM);

    init_kernel<<<BNC / 256, 256>>>(f);
    esq_kernel<<<(KCODE * 32) / 256, 256>>>(emb);

    for (int pn = 1; pn <= NTOK; pn++) {
        int rows = BATCH * pn;
        pool_kernel<<<rows, 256>>>(pn);
        dim3 dg(rows / 128, KCODE / 128);
        dist_kernel<<<dg, 256, DIST_SMEM>>>(emb);
        argmin_reduce_kernel<<<rows / 8, dim3(32, 8)>>>();
        update_kernel<<<BATCH * NTOK, 256>>>(f, emb, pn, pn - 1);
    }

    out_main_kernel<<<BNC / 256, 256>>>(f, out);
    out_scalar_kernel<<<1, 32>>>(out);
}